// round 11
// baseline (speedup 1.0000x reference)
#include <cuda_runtime.h>
#include <cstdint>

#define NNODES 50000
#define NEDGES 800000
#define MTILES 391
#define NPAD   (MTILES*128)   // 50048
#define HDIM   128
#define OUTC   64
#define SCAN_B 98             // ceil(50000/512)

// ------------- scratch: __device__ globals, touched ONLY from device code --
__device__ __align__(16) float g_z[(size_t)NPAD*HDIM];
__device__ __align__(16) float g_t[(size_t)NPAD*HDIM];
__device__ __align__(16) float g_h[(size_t)NPAD*HDIM];
__device__ __align__(16) float g_logits[(size_t)NPAD*OUTC];
__device__ int   g_cnt[NNODES];
__device__ int   g_fill[NNODES];
__device__ int   g_rowptr[NNODES+1];
__device__ int   g_srcs[NEDGES];
__device__ int   g_bsums[SCAN_B];
__device__ int   g_is64;          // 1 if edge_index is int64, 0 if int32

// Compile-time buffer selection resolved in DEVICE code.
// 0=g_z 1=g_t 2=g_h 3=g_logits
template<int ID> __device__ __forceinline__ float* buf(){
    if constexpr (ID == 0) return g_z;
    else if constexpr (ID == 1) return g_t;
    else if constexpr (ID == 2) return g_h;
    else return g_logits;
}

__device__ __forceinline__ int clampN(int i){
    i = max(i, 0);
    return min(i, NNODES - 1);
}

// Edge accessors: layout is (2, E) row-major for either dtype.
__device__ __forceinline__ int edge_src(const void* ei, int e){
    if (g_is64) return clampN((int)((const long long*)ei)[e]);
    return clampN(((const int*)ei)[e]);
}
__device__ __forceinline__ int edge_dst(const void* ei, int e){
    if (g_is64) return clampN((int)((const long long*)ei)[NEDGES + e]);
    return clampN(((const int*)ei)[NEDGES + e]);
}

// ---------------- dtype detection + init -----------------------------------
// Node ids < 50000 < 2^31: if the buffer is little-endian int64, every odd
// 32-bit word is a zero high-half. If int32, odd words are random ids
// (~half nonzero). First 4096 int32 words = 16KB, in-bounds either way.
__global__ void k_detect(const int* __restrict__ ei32){
    if (blockIdx.x == 0 && threadIdx.x == 0){
        int is64 = 1;
        for (int i = 0; i < 2048; ++i){
            if (ei32[2*i + 1] != 0){ is64 = 0; break; }
        }
        g_is64 = is64;
    }
}

// ---------------- CSR build ------------------------------------------------
__global__ void k_zero(){
    int i = blockIdx.x*blockDim.x + threadIdx.x;
    if (i < NNODES){ g_cnt[i] = 0; g_fill[i] = 0; }
}

__global__ void k_hist(const void* __restrict__ ei){
    int e = blockIdx.x*blockDim.x + threadIdx.x;
    if (e < NEDGES){
        atomicAdd(&g_cnt[edge_dst(ei, e)], 1);
    }
}

__global__ void k_scan1(){
    __shared__ int s[512];
    int i = blockIdx.x*512 + threadIdx.x;
    s[threadIdx.x] = (i < NNODES) ? g_cnt[i] : 0;
    __syncthreads();
    for (int st = 256; st > 0; st >>= 1){
        if (threadIdx.x < st) s[threadIdx.x] += s[threadIdx.x + st];
        __syncthreads();
    }
    if (threadIdx.x == 0) g_bsums[blockIdx.x] = s[0];
}

__global__ void k_scan2(){
    if (threadIdx.x == 0 && blockIdx.x == 0){
        int acc = 0;
        for (int i = 0; i < SCAN_B; ++i){ int v = g_bsums[i]; g_bsums[i] = acc; acc += v; }
    }
}

__global__ void k_scan3(){
    __shared__ int s[512];
    int i = blockIdx.x*512 + threadIdx.x;
    int v = (i < NNODES) ? g_cnt[i] : 0;
    s[threadIdx.x] = v;
    __syncthreads();
    for (int st = 1; st < 512; st <<= 1){
        int t = 0;
        if (threadIdx.x >= st) t = s[threadIdx.x - st];
        __syncthreads();
        s[threadIdx.x] += t;
        __syncthreads();
    }
    if (i < NNODES) g_rowptr[i] = g_bsums[blockIdx.x] + s[threadIdx.x] - v;  // exclusive
    if (i == NNODES-1) g_rowptr[NNODES] = NEDGES;
}

__global__ void k_scatter(const void* __restrict__ ei){
    int e = blockIdx.x*blockDim.x + threadIdx.x;
    if (e < NEDGES){
        int d = edge_dst(ei, e);
        int s = edge_src(ei, e);
        int p = atomicAdd(&g_fill[d], 1);
        int idx = g_rowptr[d] + p;
        if (idx >= 0 && idx < NEDGES) g_srcs[idx] = s;
    }
}

// ---------------- GIN aggregation: g_z = (1+eps)*h + sum_{j in N(i)} h_j ---
// warp per node, 4 floats per lane. Input: x param (layer1) or g_h (layer2).
template<bool FROM_X>
__global__ void k_agg(const float* __restrict__ xin, const float* __restrict__ epsp){
    int gw   = (blockIdx.x*blockDim.x + threadIdx.x) >> 5;
    int lane = threadIdx.x & 31;
    if (gw >= NNODES) return;
    const float* Hin = FROM_X ? xin : buf<2>();
    float scale = 1.0f + *epsp;
    const float4* hv = (const float4*)Hin;
    float4 self = hv[(size_t)gw*32 + lane];
    float4 acc;
    acc.x = self.x*scale; acc.y = self.y*scale;
    acc.z = self.z*scale; acc.w = self.w*scale;
    int p  = g_rowptr[gw];
    int pe = g_rowptr[gw + 1];
    for (; p < pe; ++p){
        int s = g_srcs[p];
        float4 v = hv[(size_t)s*32 + lane];
        acc.x += v.x; acc.y += v.y; acc.z += v.z; acc.w += v.w;
    }
    ((float4*)buf<0>())[(size_t)gw*32 + lane] = acc;
}

// ---------------- fused GEMM + bias (+ relu) -------------------------------
// dst[m][n] = act( sum_k src[m][k]*W[k][n] + bias[n] ), K = 128 fixed.
// 256 threads (16x16), tile 128 x NC, per-thread 8 x (NC/16).
// K in 4 chunks of 32 through static smem (~33KB). M padded -> no guards.
template<int SRC, int DST, int NC, bool RELU>
__global__ void __launch_bounds__(256)
k_gemm(const float* __restrict__ W, const float* __restrict__ bias){
    constexpr int CPT = NC/16;          // cols per thread: 8 or 4
    __shared__ float As[32][129];       // k-major, padded (conflict-free)
    __shared__ float Ws[32][NC];

    const int tid = threadIdx.x;
    const int tx  = tid & 15;
    const int ty  = tid >> 4;

    float acc[8][CPT];
    {
        float b[CPT];
        #pragma unroll
        for (int c = 0; c < CPT; c += 4){
            float4 bv = *(const float4*)(bias + tx*CPT + c);
            b[c] = bv.x; b[c+1] = bv.y; b[c+2] = bv.z; b[c+3] = bv.w;
        }
        #pragma unroll
        for (int r = 0; r < 8; ++r)
            #pragma unroll
            for (int c = 0; c < CPT; ++c) acc[r][c] = b[c];
    }

    const float* Ablk = buf<SRC>() + (size_t)blockIdx.x * 128 * 128;

    #pragma unroll
    for (int kc = 0; kc < 4; ++kc){
        // stage A chunk [128 rows][32 ks], transposed into As[k][m]
        #pragma unroll
        for (int j = 0; j < 4; ++j){
            int idx = tid + j*256;          // 0..1023
            int row = idx >> 3;
            int c4  = idx & 7;
            float4 v = *(const float4*)(Ablk + row*128 + kc*32 + c4*4);
            As[c4*4+0][row] = v.x;
            As[c4*4+1][row] = v.y;
            As[c4*4+2][row] = v.z;
            As[c4*4+3][row] = v.w;
        }
        // stage W chunk [32 ks][NC cols]
        #pragma unroll
        for (int j = 0; j < (32*NC/4)/256; ++j){
            int idx = tid + j*256;
            int row = idx / (NC/4);
            int c4  = idx % (NC/4);
            *(float4*)&Ws[row][c4*4] = *(const float4*)(W + (kc*32+row)*NC + c4*4);
        }
        __syncthreads();

        #pragma unroll
        for (int k = 0; k < 32; ++k){
            float a[8];
            #pragma unroll
            for (int r = 0; r < 8; ++r) a[r] = As[k][ty*8 + r];
            float w[CPT];
            #pragma unroll
            for (int c = 0; c < CPT; c += 4){
                float4 wv = *(const float4*)&Ws[k][tx*CPT + c];
                w[c] = wv.x; w[c+1] = wv.y; w[c+2] = wv.z; w[c+3] = wv.w;
            }
            #pragma unroll
            for (int r = 0; r < 8; ++r)
                #pragma unroll
                for (int c = 0; c < CPT; ++c)
                    acc[r][c] += a[r]*w[c];
        }
        __syncthreads();
    }

    float* Og = buf<DST>() + (size_t)blockIdx.x * 128 * NC;
    #pragma unroll
    for (int r = 0; r < 8; ++r){
        int row = ty*8 + r;
        #pragma unroll
        for (int c = 0; c < CPT; c += 4){
            float4 v;
            v.x = acc[r][c];   v.y = acc[r][c+1];
            v.z = acc[r][c+2]; v.w = acc[r][c+3];
            if (RELU){
                v.x = fmaxf(v.x, 0.f); v.y = fmaxf(v.y, 0.f);
                v.z = fmaxf(v.z, 0.f); v.w = fmaxf(v.w, 0.f);
            }
            *(float4*)(Og + row*NC + tx*CPT + c) = v;
        }
    }
}

// ---------------- log_softmax over 64 cols, warp per row -------------------
__global__ void k_lsm(float* __restrict__ out){
    int gw   = (blockIdx.x*blockDim.x + threadIdx.x) >> 5;
    int lane = threadIdx.x & 31;
    if (gw >= NNODES) return;
    const float* row = buf<3>() + (size_t)gw*OUTC;
    float a = row[lane];
    float b = row[lane + 32];
    float m = fmaxf(a, b);
    #pragma unroll
    for (int o = 16; o > 0; o >>= 1) m = fmaxf(m, __shfl_xor_sync(0xffffffffu, m, o));
    float s = expf(a - m) + expf(b - m);
    #pragma unroll
    for (int o = 16; o > 0; o >>= 1) s += __shfl_xor_sync(0xffffffffu, s, o);
    float ls = m + logf(s);
    float* orow = out + (size_t)gw*OUTC;
    orow[lane]      = a - ls;
    orow[lane + 32] = b - ls;
}

// ---------------- launch: kernel launches ONLY, size-based input mapping ---
extern "C" void kernel_launch(void* const* d_in, const int* in_sizes, int n_in,
                              void* d_out, int out_size){
    // Classify inputs by element count (robust to metadata ordering).
    // Unique sizes: x=6400000, edge_index=1600000, Wl=8192, bl=64.
    // Size classes (same relative order under dict order or alphabetical):
    // eps{1,2}=1, W{11,12,21,22}=16384, b{11,12,21,22}=128.
    const float* x = 0; const void* ei = 0;
    const float* Wl = 0; const float* bl = 0;
    const float* epsv[2] = {0,0};
    const float* Wv[4]   = {0,0,0,0};
    const float* bv[4]   = {0,0,0,0};
    int neps = 0, nW = 0, nb = 0;
    for (int i = 0; i < n_in; ++i){
        long long s = in_sizes[i];
        if      (s == 6400000) x  = (const float*)d_in[i];
        else if (s == 1600000) ei = d_in[i];
        else if (s == 8192)    Wl = (const float*)d_in[i];
        else if (s == 64)      bl = (const float*)d_in[i];
        else if (s == 1   && neps < 2) epsv[neps++] = (const float*)d_in[i];
        else if (s == 16384 && nW < 4) Wv[nW++]     = (const float*)d_in[i];
        else if (s == 128  && nb  < 4) bv[nb++]     = (const float*)d_in[i];
    }
    if (!x || !ei || !Wl || !bl || neps < 2 || nW < 4 || nb < 4) return;
    float* out = (float*)d_out;

    const int EB = (NEDGES + 255) / 256;
    const int WB = (NNODES*32 + 255) / 256;   // warp-per-node launches

    // dtype detection + CSR build (per launch)
    k_detect <<<1, 32>>>((const int*)ei);
    k_zero   <<<(NNODES + 255)/256, 256>>>();
    k_hist   <<<EB, 256>>>(ei);
    k_scan1  <<<SCAN_B, 512>>>();
    k_scan2  <<<1, 32>>>();
    k_scan3  <<<SCAN_B, 512>>>();
    k_scatter<<<EB, 256>>>(ei);

    // layer 1: z = agg(x); t = relu(z@W11+b11); h = relu(t@W12+b12)
    k_agg<true> <<<WB, 256>>>(x, epsv[0]);
    k_gemm<0,1,128,true><<<MTILES, 256>>>(Wv[0], bv[0]);
    k_gemm<1,2,128,true><<<MTILES, 256>>>(Wv[1], bv[1]);

    // layer 2: z = agg(h); t = relu(z@W21+b21); h = relu(t@W22+b22)
    k_agg<false><<<WB, 256>>>(x, epsv[1]);
    k_gemm<0,1,128,true><<<MTILES, 256>>>(Wv[2], bv[2]);
    k_gemm<1,2,128,true><<<MTILES, 256>>>(Wv[3], bv[3]);

    // classifier + log_softmax
    k_gemm<2,3,64,false><<<MTILES, 256>>>(Wl, bl);
    k_lsm<<<WB, 256>>>(out);
}

// round 12
// speedup vs baseline: 1.9220x; 1.9220x over previous
#include <cuda_runtime.h>
#include <cstdint>

#define NNODES 50000
#define NEDGES 800000
#define MTILES 391
#define NPAD   (MTILES*128)   // 50048
#define HDIM   128
#define OUTC   64
#define SCAN_B 98             // ceil(50000/512)
#define WSPLIT_TOT (4*16384 + 8192)   // 73728

// ------------- scratch: __device__ globals, touched ONLY from device code --
__device__ __align__(16) float g_z[(size_t)NPAD*HDIM];
__device__ __align__(16) float g_t[(size_t)NPAD*HDIM];
__device__ __align__(16) float g_h[(size_t)NPAD*HDIM];
__device__ __align__(16) float g_logits[(size_t)NPAD*OUTC];
__device__ __align__(16) float g_whi[WSPLIT_TOT];
__device__ __align__(16) float g_wlo[WSPLIT_TOT];
__device__ int   g_cnt[NNODES];
__device__ int   g_fill[NNODES];
__device__ int   g_rowptr[NNODES+1];
__device__ int   g_srcs[NEDGES];
__device__ int   g_bsums[SCAN_B];
__device__ int   g_is64;          // 1 if edge_index is int64, 0 if int32

// Compile-time buffer selection resolved in DEVICE code.
// 0=g_z 1=g_t 2=g_h 3=g_logits
template<int ID> __device__ __forceinline__ float* buf(){
    if constexpr (ID == 0) return g_z;
    else if constexpr (ID == 1) return g_t;
    else if constexpr (ID == 2) return g_h;
    else return g_logits;
}

__device__ __forceinline__ int clampN(int i){
    i = max(i, 0);
    return min(i, NNODES - 1);
}

// Edge accessors: layout is (2, E) row-major for either dtype.
__device__ __forceinline__ int edge_src(const void* ei, int e){
    if (g_is64) return clampN((int)((const long long*)ei)[e]);
    return clampN(((const int*)ei)[e]);
}
__device__ __forceinline__ int edge_dst(const void* ei, int e){
    if (g_is64) return clampN((int)((const long long*)ei)[NEDGES + e]);
    return clampN(((const int*)ei)[NEDGES + e]);
}

__device__ __forceinline__ uint32_t f2tf32(float f){
    uint32_t u;
    asm("cvt.rna.tf32.f32 %0, %1;" : "=r"(u) : "f"(f));
    return u;
}

__device__ __forceinline__ void mma8(float* c, uint32_t a0, uint32_t a1,
                                     uint32_t a2, uint32_t a3,
                                     uint32_t b0, uint32_t b1){
    asm("mma.sync.aligned.m16n8k8.row.col.f32.tf32.tf32.f32 "
        "{%0,%1,%2,%3},{%4,%5,%6,%7},{%8,%9},{%0,%1,%2,%3};"
        : "+f"(c[0]), "+f"(c[1]), "+f"(c[2]), "+f"(c[3])
        : "r"(a0), "r"(a1), "r"(a2), "r"(a3), "r"(b0), "r"(b1));
}

// ---------------- dtype detection ------------------------------------------
__global__ void k_detect(const int* __restrict__ ei32){
    if (blockIdx.x == 0 && threadIdx.x == 0){
        int is64 = 1;
        for (int i = 0; i < 2048; ++i){
            if (ei32[2*i + 1] != 0){ is64 = 0; break; }
        }
        g_is64 = is64;
    }
}

// ---------------- weight split into tf32 hi/lo -----------------------------
// regions: [0)=W11 [16384)=W12 [32768)=W21 [49152)=W22 [65536..73728)=Wl
__global__ void k_wsplit(const float* __restrict__ W0, const float* __restrict__ W1,
                         const float* __restrict__ W2, const float* __restrict__ W3,
                         const float* __restrict__ W4){
    int i = blockIdx.x*blockDim.x + threadIdx.x;
    if (i >= WSPLIT_TOT) return;
    const float* src; int off;
    if      (i < 16384){ src = W0; off = i; }
    else if (i < 32768){ src = W1; off = i - 16384; }
    else if (i < 49152){ src = W2; off = i - 32768; }
    else if (i < 65536){ src = W3; off = i - 49152; }
    else               { src = W4; off = i - 65536; }
    float w  = src[off];
    float hf = __uint_as_float(f2tf32(w));
    g_whi[i] = hf;
    g_wlo[i] = __uint_as_float(f2tf32(w - hf));
}

// ---------------- CSR build ------------------------------------------------
__global__ void k_zero(){
    int i = blockIdx.x*blockDim.x + threadIdx.x;
    if (i < NNODES){ g_cnt[i] = 0; g_fill[i] = 0; }
}

__global__ void k_hist(const void* __restrict__ ei){
    int e = blockIdx.x*blockDim.x + threadIdx.x;
    if (e < NEDGES) atomicAdd(&g_cnt[edge_dst(ei, e)], 1);
}

__global__ void k_scan1(){
    __shared__ int s[512];
    int i = blockIdx.x*512 + threadIdx.x;
    s[threadIdx.x] = (i < NNODES) ? g_cnt[i] : 0;
    __syncthreads();
    for (int st = 256; st > 0; st >>= 1){
        if (threadIdx.x < st) s[threadIdx.x] += s[threadIdx.x + st];
        __syncthreads();
    }
    if (threadIdx.x == 0) g_bsums[blockIdx.x] = s[0];
}

__global__ void k_scan2(){
    if (threadIdx.x == 0 && blockIdx.x == 0){
        int acc = 0;
        for (int i = 0; i < SCAN_B; ++i){ int v = g_bsums[i]; g_bsums[i] = acc; acc += v; }
    }
}

__global__ void k_scan3(){
    __shared__ int s[512];
    int i = blockIdx.x*512 + threadIdx.x;
    int v = (i < NNODES) ? g_cnt[i] : 0;
    s[threadIdx.x] = v;
    __syncthreads();
    for (int st = 1; st < 512; st <<= 1){
        int t = 0;
        if (threadIdx.x >= st) t = s[threadIdx.x - st];
        __syncthreads();
        s[threadIdx.x] += t;
        __syncthreads();
    }
    if (i < NNODES) g_rowptr[i] = g_bsums[blockIdx.x] + s[threadIdx.x] - v;  // exclusive
    if (i == NNODES-1) g_rowptr[NNODES] = NEDGES;
}

__global__ void k_scatter(const void* __restrict__ ei){
    int e = blockIdx.x*blockDim.x + threadIdx.x;
    if (e < NEDGES){
        int d = edge_dst(ei, e);
        int s = edge_src(ei, e);
        int p = atomicAdd(&g_fill[d], 1);
        int idx = g_rowptr[d] + p;
        if (idx >= 0 && idx < NEDGES) g_srcs[idx] = s;
    }
}

// ---------------- GIN aggregation: g_z = (1+eps)*h + sum_{j in N(i)} h_j ---
template<bool FROM_X>
__global__ void k_agg(const float* __restrict__ xin, const float* __restrict__ epsp){
    int gw   = (blockIdx.x*blockDim.x + threadIdx.x) >> 5;
    int lane = threadIdx.x & 31;
    if (gw >= NNODES) return;
    const float* Hin = FROM_X ? xin : buf<2>();
    float scale = 1.0f + *epsp;
    const float4* hv = (const float4*)Hin;
    float4 self = hv[(size_t)gw*32 + lane];
    float4 acc;
    acc.x = self.x*scale; acc.y = self.y*scale;
    acc.z = self.z*scale; acc.w = self.w*scale;
    int p  = g_rowptr[gw];
    int pe = g_rowptr[gw + 1];
    for (; p < pe; ++p){
        int s = g_srcs[p];
        float4 v = hv[(size_t)s*32 + lane];
        acc.x += v.x; acc.y += v.y; acc.z += v.z; acc.w += v.w;
    }
    ((float4*)buf<0>())[(size_t)gw*32 + lane] = acc;
}

// ---------------- tensor-core GEMM (split-TF32, 3 MMAs) --------------------
// dst[m][n] = act( sum_k src[m][k]*W[k][n] + bias[n] ), K = 128.
// Block 256 thr = 8 warps; tile 128 x NC. Warp: 32 m x (NC/2) n.
// K in 8 chunks of 16 via smem. W pre-split (g_whi/g_wlo), A split in regs.
// err ~ 2^-22 (lo*lo term dropped).
template<int SRC, int DST, int NC, bool RELU>
__global__ void __launch_bounds__(256)
k_mma(int woff, const float* __restrict__ bias){
    constexpr int NT = NC/16;            // n-tiles (8 wide) per warp: 8 or 4
    __shared__ float As[16][136];        // k-major (transposed), stride 136
    __shared__ float Wh[16][136];
    __shared__ float Wl_[16][136];

    const int tid  = threadIdx.x;
    const int wid  = tid >> 5;
    const int lane = tid & 31;
    const int qr   = lane >> 2;          // 0..7
    const int qc   = lane & 3;           // 0..3
    const int wm   = (wid & 3) * 32;     // warp m offset
    const int wn   = (wid >> 2) * (NC/2);// warp n offset

    float acc[2][NT][4];
    #pragma unroll
    for (int nt = 0; nt < NT; ++nt){
        float b0 = bias[wn + nt*8 + qc*2];
        float b1 = bias[wn + nt*8 + qc*2 + 1];
        #pragma unroll
        for (int mt = 0; mt < 2; ++mt){
            acc[mt][nt][0] = b0; acc[mt][nt][1] = b1;
            acc[mt][nt][2] = b0; acc[mt][nt][3] = b1;
        }
    }

    const float* Ablk = buf<SRC>() + (size_t)blockIdx.x * 128 * 128;
    const float* Whg  = g_whi + woff;
    const float* Wlg  = g_wlo + woff;

    for (int kc = 0; kc < 8; ++kc){
        // stage A chunk [128 m][16 k] -> As[k][m] (transposed)
        #pragma unroll
        for (int j = 0; j < 2; ++j){
            int idx = tid + j*256;       // 0..511
            int row = idx >> 2;
            int c4  = idx & 3;
            float4 v = *(const float4*)(Ablk + row*128 + kc*16 + c4*4);
            As[c4*4+0][row] = v.x;
            As[c4*4+1][row] = v.y;
            As[c4*4+2][row] = v.z;
            As[c4*4+3][row] = v.w;
        }
        // stage W hi/lo chunk [16 k][NC n]
        #pragma unroll
        for (int j = 0; j < (16*NC/4 + 255)/256; ++j){
            int idx = tid + j*256;
            if (16*NC/4 % 256 == 0 || idx < 16*NC/4){
                int row = idx / (NC/4);
                int c4  = idx % (NC/4);
                *(float4*)&Wh [row][c4*4] = *(const float4*)(Whg + (kc*16+row)*NC + c4*4);
                *(float4*)&Wl_[row][c4*4] = *(const float4*)(Wlg + (kc*16+row)*NC + c4*4);
            }
        }
        __syncthreads();

        #pragma unroll
        for (int ks = 0; ks < 2; ++ks){
            const int kk = ks*8;
            // A fragments for 2 m-tiles, split hi/lo in regs
            uint32_t ah[2][4], al[2][4];
            #pragma unroll
            for (int mt = 0; mt < 2; ++mt){
                int m0 = wm + mt*16 + qr;
                float f0 = As[kk + qc    ][m0];
                float f1 = As[kk + qc    ][m0 + 8];
                float f2 = As[kk + qc + 4][m0];
                float f3 = As[kk + qc + 4][m0 + 8];
                uint32_t h0 = f2tf32(f0), h1 = f2tf32(f1), h2 = f2tf32(f2), h3 = f2tf32(f3);
                ah[mt][0]=h0; ah[mt][1]=h1; ah[mt][2]=h2; ah[mt][3]=h3;
                al[mt][0]=f2tf32(f0 - __uint_as_float(h0));
                al[mt][1]=f2tf32(f1 - __uint_as_float(h1));
                al[mt][2]=f2tf32(f2 - __uint_as_float(h2));
                al[mt][3]=f2tf32(f3 - __uint_as_float(h3));
            }
            // B fragments (pre-split)
            uint32_t bh[NT][2], bl[NT][2];
            #pragma unroll
            for (int nt = 0; nt < NT; ++nt){
                int n0 = wn + nt*8 + qr;
                bh[nt][0] = __float_as_uint(Wh [kk + qc    ][n0]);
                bh[nt][1] = __float_as_uint(Wh [kk + qc + 4][n0]);
                bl[nt][0] = __float_as_uint(Wl_[kk + qc    ][n0]);
                bl[nt][1] = __float_as_uint(Wl_[kk + qc + 4][n0]);
            }
            #pragma unroll
            for (int mt = 0; mt < 2; ++mt)
                #pragma unroll
                for (int nt = 0; nt < NT; ++nt){
                    mma8(acc[mt][nt], ah[mt][0],ah[mt][1],ah[mt][2],ah[mt][3], bh[nt][0],bh[nt][1]);
                    mma8(acc[mt][nt], ah[mt][0],ah[mt][1],ah[mt][2],ah[mt][3], bl[nt][0],bl[nt][1]);
                    mma8(acc[mt][nt], al[mt][0],al[mt][1],al[mt][2],al[mt][3], bh[nt][0],bh[nt][1]);
                }
        }
        __syncthreads();
    }

    float* Og = buf<DST>() + (size_t)blockIdx.x * 128 * NC;
    #pragma unroll
    for (int mt = 0; mt < 2; ++mt){
        #pragma unroll
        for (int nt = 0; nt < NT; ++nt){
            int row = wm + mt*16 + qr;
            int col = wn + nt*8 + qc*2;
            float2 v0 = make_float2(acc[mt][nt][0], acc[mt][nt][1]);
            float2 v1 = make_float2(acc[mt][nt][2], acc[mt][nt][3]);
            if (RELU){
                v0.x = fmaxf(v0.x, 0.f); v0.y = fmaxf(v0.y, 0.f);
                v1.x = fmaxf(v1.x, 0.f); v1.y = fmaxf(v1.y, 0.f);
            }
            *(float2*)(Og + (row    )*NC + col) = v0;
            *(float2*)(Og + (row + 8)*NC + col) = v1;
        }
    }
}

// ---------------- log_softmax over 64 cols, warp per row -------------------
__global__ void k_lsm(float* __restrict__ out){
    int gw   = (blockIdx.x*blockDim.x + threadIdx.x) >> 5;
    int lane = threadIdx.x & 31;
    if (gw >= NNODES) return;
    const float* row = buf<3>() + (size_t)gw*OUTC;
    float a = row[lane];
    float b = row[lane + 32];
    float m = fmaxf(a, b);
    #pragma unroll
    for (int o = 16; o > 0; o >>= 1) m = fmaxf(m, __shfl_xor_sync(0xffffffffu, m, o));
    float s = expf(a - m) + expf(b - m);
    #pragma unroll
    for (int o = 16; o > 0; o >>= 1) s += __shfl_xor_sync(0xffffffffu, s, o);
    float ls = m + logf(s);
    float* orow = out + (size_t)gw*OUTC;
    orow[lane]      = a - ls;
    orow[lane + 32] = b - ls;
}

// ---------------- launch: kernel launches ONLY, size-based input mapping ---
extern "C" void kernel_launch(void* const* d_in, const int* in_sizes, int n_in,
                              void* d_out, int out_size){
    const float* x = 0; const void* ei = 0;
    const float* Wl = 0; const float* bl = 0;
    const float* epsv[2] = {0,0};
    const float* Wv[4]   = {0,0,0,0};
    const float* bv[4]   = {0,0,0,0};
    int neps = 0, nW = 0, nb = 0;
    for (int i = 0; i < n_in; ++i){
        long long s = in_sizes[i];
        if      (s == 6400000) x  = (const float*)d_in[i];
        else if (s == 1600000) ei = d_in[i];
        else if (s == 8192)    Wl = (const float*)d_in[i];
        else if (s == 64)      bl = (const float*)d_in[i];
        else if (s == 1   && neps < 2) epsv[neps++] = (const float*)d_in[i];
        else if (s == 16384 && nW < 4) Wv[nW++]     = (const float*)d_in[i];
        else if (s == 128  && nb  < 4) bv[nb++]     = (const float*)d_in[i];
    }
    if (!x || !ei || !Wl || !bl || neps < 2 || nW < 4 || nb < 4) return;
    float* out = (float*)d_out;

    const int EB = (NEDGES + 255) / 256;
    const int WB = (NNODES*32 + 255) / 256;

    // dtype detection + weight split + CSR build (per launch)
    k_detect <<<1, 32>>>((const int*)ei);
    k_wsplit <<<(WSPLIT_TOT + 255)/256, 256>>>(Wv[0], Wv[1], Wv[2], Wv[3], Wl);
    k_zero   <<<(NNODES + 255)/256, 256>>>();
    k_hist   <<<EB, 256>>>(ei);
    k_scan1  <<<SCAN_B, 512>>>();
    k_scan2  <<<1, 32>>>();
    k_scan3  <<<SCAN_B, 512>>>();
    k_scatter<<<EB, 256>>>(ei);

    // layer 1: z = agg(x); t = relu(z@W11+b11); h = relu(t@W12+b12)
    k_agg<true> <<<WB, 256>>>(x, epsv[0]);
    k_mma<0,1,128,true><<<MTILES, 256>>>(0,     bv[0]);
    k_mma<1,2,128,true><<<MTILES, 256>>>(16384, bv[1]);

    // layer 2: z = agg(h); t = relu(z@W21+b21); h = relu(t@W22+b22)
    k_agg<false><<<WB, 256>>>(x, epsv[1]);
    k_mma<0,1,128,true><<<MTILES, 256>>>(32768, bv[2]);
    k_mma<1,2,128,true><<<MTILES, 256>>>(49152, bv[3]);

    // classifier + log_softmax
    k_mma<2,3,64,false><<<MTILES, 256>>>(65536, bl);
    k_lsm<<<WB, 256>>>(out);
}

// round 13
// speedup vs baseline: 1.9222x; 1.0001x over previous
#include <cuda_runtime.h>
#include <cstdint>

#define NNODES 50000
#define NEDGES 800000
#define MTILES 391
#define NPAD   (MTILES*128)   // 50048
#define HDIM   128
#define OUTC   64
#define SCAN_B 98             // ceil(50000/512)
#define WSPLIT_TOT (4*16384 + 8192)   // 73728
#define ZERO_B 196            // ceil(50000/256)
#define WSPL_B 288            // ceil(73728/256)

// ------------- scratch: __device__ globals, touched ONLY from device code --
__device__ __align__(16) float g_z[(size_t)NPAD*HDIM];
__device__ __align__(16) float g_t[(size_t)NPAD*HDIM];
__device__ __align__(16) float g_h[(size_t)NPAD*HDIM];
__device__ __align__(16) float g_whi[WSPLIT_TOT];
__device__ __align__(16) float g_wlo[WSPLIT_TOT];
__device__ int   g_cnt[NNODES];
__device__ int   g_fill[NNODES];
__device__ int   g_rowptr[NNODES+1];
__device__ int   g_srcs[NEDGES];
__device__ int   g_bsums[SCAN_B];
__device__ int   g_is64;          // 1 if edge_index is int64, 0 if int32

// 0=g_z 1=g_t 2=g_h
template<int ID> __device__ __forceinline__ float* buf(){
    if constexpr (ID == 0) return g_z;
    else if constexpr (ID == 1) return g_t;
    else return g_h;
}

__device__ __forceinline__ int clampN(int i){
    i = max(i, 0);
    return min(i, NNODES - 1);
}

__device__ __forceinline__ int edge_src(const void* ei, int e){
    if (g_is64) return clampN((int)((const long long*)ei)[e]);
    return clampN(((const int*)ei)[e]);
}
__device__ __forceinline__ int edge_dst(const void* ei, int e){
    if (g_is64) return clampN((int)((const long long*)ei)[NEDGES + e]);
    return clampN(((const int*)ei)[NEDGES + e]);
}

__device__ __forceinline__ uint32_t f2tf32(float f){
    uint32_t u;
    asm("cvt.rna.tf32.f32 %0, %1;" : "=r"(u) : "f"(f));
    return u;
}

__device__ __forceinline__ void mma8(float* c, uint32_t a0, uint32_t a1,
                                     uint32_t a2, uint32_t a3,
                                     uint32_t b0, uint32_t b1){
    asm("mma.sync.aligned.m16n8k8.row.col.f32.tf32.tf32.f32 "
        "{%0,%1,%2,%3},{%4,%5,%6,%7},{%8,%9},{%0,%1,%2,%3};"
        : "+f"(c[0]), "+f"(c[1]), "+f"(c[2]), "+f"(c[3])
        : "r"(a0), "r"(a1), "r"(a2), "r"(a3), "r"(b0), "r"(b1));
}

// ---------------- fused init: detect dtype + zero counters + split weights --
// block 0: dtype detect (parallel).  blocks [1,1+ZERO_B): zero cnt/fill.
// blocks [1+ZERO_B, 1+ZERO_B+WSPL_B): tf32 hi/lo split of all weights.
// weight regions in g_whi/g_wlo: [0)=W11 [16384)=W12 [32768)=W21 [49152)=W22 [65536)=Wl
__global__ void k_init(const int* __restrict__ ei32,
                       const float* __restrict__ W0, const float* __restrict__ W1,
                       const float* __restrict__ W2, const float* __restrict__ W3,
                       const float* __restrict__ W4){
    int bid = blockIdx.x;
    if (bid == 0){
        __shared__ int anynz;
        if (threadIdx.x == 0) anynz = 0;
        __syncthreads();
        bool nz = false;
        #pragma unroll
        for (int j = 0; j < 8; ++j){
            int i = threadIdx.x*8 + j;          // i < 2048
            if (ei32[2*i + 1] != 0) nz = true;
        }
        if (__ballot_sync(0xffffffffu, nz) && (threadIdx.x & 31) == 0)
            atomicExch(&anynz, 1);
        __syncthreads();
        if (threadIdx.x == 0) g_is64 = anynz ? 0 : 1;
    } else if (bid < 1 + ZERO_B){
        int i = (bid - 1)*256 + threadIdx.x;
        if (i < NNODES){ g_cnt[i] = 0; g_fill[i] = 0; }
    } else {
        int i = (bid - 1 - ZERO_B)*256 + threadIdx.x;
        if (i < WSPLIT_TOT){
            const float* src; int off;
            if      (i < 16384){ src = W0; off = i; }
            else if (i < 32768){ src = W1; off = i - 16384; }
            else if (i < 49152){ src = W2; off = i - 32768; }
            else if (i < 65536){ src = W3; off = i - 49152; }
            else               { src = W4; off = i - 65536; }
            float w  = src[off];
            float hf = __uint_as_float(f2tf32(w));
            g_whi[i] = hf;
            g_wlo[i] = __uint_as_float(f2tf32(w - hf));
        }
    }
}

// ---------------- CSR build ------------------------------------------------
__global__ void k_hist(const void* __restrict__ ei){
    int e = blockIdx.x*blockDim.x + threadIdx.x;
    if (e < NEDGES) atomicAdd(&g_cnt[edge_dst(ei, e)], 1);
}

__global__ void k_scan1(){
    __shared__ int s[512];
    int i = blockIdx.x*512 + threadIdx.x;
    s[threadIdx.x] = (i < NNODES) ? g_cnt[i] : 0;
    __syncthreads();
    for (int st = 256; st > 0; st >>= 1){
        if (threadIdx.x < st) s[threadIdx.x] += s[threadIdx.x + st];
        __syncthreads();
    }
    if (threadIdx.x == 0) g_bsums[blockIdx.x] = s[0];
}

// block-level scan + serial lookback over prior block sums (scan2 folded in)
__global__ void k_scan3(){
    __shared__ int s[512];
    __shared__ int base;
    int i = blockIdx.x*512 + threadIdx.x;
    int v = (i < NNODES) ? g_cnt[i] : 0;
    s[threadIdx.x] = v;
    if (threadIdx.x == 0){
        int acc = 0;
        for (int j = 0; j < blockIdx.x; ++j) acc += g_bsums[j];
        base = acc;
    }
    __syncthreads();
    for (int st = 1; st < 512; st <<= 1){
        int t = 0;
        if (threadIdx.x >= st) t = s[threadIdx.x - st];
        __syncthreads();
        s[threadIdx.x] += t;
        __syncthreads();
    }
    if (i < NNODES) g_rowptr[i] = base + s[threadIdx.x] - v;  // exclusive
    if (i == NNODES-1) g_rowptr[NNODES] = NEDGES;
}

__global__ void k_scatter(const void* __restrict__ ei){
    int e = blockIdx.x*blockDim.x + threadIdx.x;
    if (e < NEDGES){
        int d = edge_dst(ei, e);
        int s = edge_src(ei, e);
        int p = atomicAdd(&g_fill[d], 1);
        int idx = g_rowptr[d] + p;
        if (idx >= 0 && idx < NEDGES) g_srcs[idx] = s;
    }
}

// ---------------- GIN aggregation: g_z = (1+eps)*h + sum_{j in N(i)} h_j ---
// warp per node; src indices loaded coalesced 32-wide, shuffle-broadcast.
template<bool FROM_X>
__global__ void k_agg(const float* __restrict__ xin, const float* __restrict__ epsp){
    int gw   = (blockIdx.x*blockDim.x + threadIdx.x) >> 5;
    int lane = threadIdx.x & 31;
    if (gw >= NNODES) return;
    const float* Hin = FROM_X ? xin : buf<2>();
    float scale = 1.0f + *epsp;
    const float4* hv = (const float4*)Hin;
    float4 self = hv[(size_t)gw*32 + lane];
    float4 acc;
    acc.x = self.x*scale; acc.y = self.y*scale;
    acc.z = self.z*scale; acc.w = self.w*scale;
    int p  = g_rowptr[gw];
    int pe = g_rowptr[gw + 1];
    while (p < pe){
        int cnt = min(pe - p, 32);
        int idx = (lane < cnt) ? g_srcs[p + lane] : 0;
        for (int j = 0; j < cnt; ++j){
            int s = __shfl_sync(0xffffffffu, idx, j);
            float4 v = hv[(size_t)s*32 + lane];
            acc.x += v.x; acc.y += v.y; acc.z += v.z; acc.w += v.w;
        }
        p += cnt;
    }
    ((float4*)buf<0>())[(size_t)gw*32 + lane] = acc;
}

// ---------------- tensor-core GEMM (split-TF32, 3 MMAs) --------------------
// dst[m][n] = relu( sum_k src[m][k]*W[k][n] + bias[n] ), K=128, NC=128.
// Block 256 thr = 8 warps (4m x 2n); warp tile 32m x 64n.
template<int SRC, int DST>
__global__ void __launch_bounds__(256)
k_mma(int woff, const float* __restrict__ bias){
    constexpr int NC = 128;
    constexpr int NT = 8;
    __shared__ float As[16][136];
    __shared__ float Wh[16][136];
    __shared__ float Wl_[16][136];

    const int tid  = threadIdx.x;
    const int wid  = tid >> 5;
    const int lane = tid & 31;
    const int qr   = lane >> 2;
    const int qc   = lane & 3;
    const int wm   = (wid & 3) * 32;
    const int wn   = (wid >> 2) * 64;

    float acc[2][NT][4];
    #pragma unroll
    for (int nt = 0; nt < NT; ++nt){
        float b0 = bias[wn + nt*8 + qc*2];
        float b1 = bias[wn + nt*8 + qc*2 + 1];
        #pragma unroll
        for (int mt = 0; mt < 2; ++mt){
            acc[mt][nt][0] = b0; acc[mt][nt][1] = b1;
            acc[mt][nt][2] = b0; acc[mt][nt][3] = b1;
        }
    }

    const float* Ablk = buf<SRC>() + (size_t)blockIdx.x * 128 * 128;
    const float* Whg  = g_whi + woff;
    const float* Wlg  = g_wlo + woff;

    for (int kc = 0; kc < 8; ++kc){
        #pragma unroll
        for (int j = 0; j < 2; ++j){
            int idx = tid + j*256;
            int row = idx >> 2;
            int c4  = idx & 3;
            float4 v = *(const float4*)(Ablk + row*128 + kc*16 + c4*4);
            As[c4*4+0][row] = v.x;
            As[c4*4+1][row] = v.y;
            As[c4*4+2][row] = v.z;
            As[c4*4+3][row] = v.w;
        }
        #pragma unroll
        for (int j = 0; j < 2; ++j){
            int idx = tid + j*256;
            int row = idx >> 5;           // /32
            int c4  = idx & 31;
            *(float4*)&Wh [row][c4*4] = *(const float4*)(Whg + (kc*16+row)*NC + c4*4);
            *(float4*)&Wl_[row][c4*4] = *(const float4*)(Wlg + (kc*16+row)*NC + c4*4);
        }
        __syncthreads();

        #pragma unroll
        for (int ks = 0; ks < 2; ++ks){
            const int kk = ks*8;
            uint32_t ah[2][4], al[2][4];
            #pragma unroll
            for (int mt = 0; mt < 2; ++mt){
                int m0 = wm + mt*16 + qr;
                float f0 = As[kk + qc    ][m0];
                float f1 = As[kk + qc    ][m0 + 8];
                float f2 = As[kk + qc + 4][m0];
                float f3 = As[kk + qc + 4][m0 + 8];
                uint32_t h0 = f2tf32(f0), h1 = f2tf32(f1), h2 = f2tf32(f2), h3 = f2tf32(f3);
                ah[mt][0]=h0; ah[mt][1]=h1; ah[mt][2]=h2; ah[mt][3]=h3;
                al[mt][0]=f2tf32(f0 - __uint_as_float(h0));
                al[mt][1]=f2tf32(f1 - __uint_as_float(h1));
                al[mt][2]=f2tf32(f2 - __uint_as_float(h2));
                al[mt][3]=f2tf32(f3 - __uint_as_float(h3));
            }
            uint32_t bh[NT][2], bl[NT][2];
            #pragma unroll
            for (int nt = 0; nt < NT; ++nt){
                int n0 = wn + nt*8 + qr;
                bh[nt][0] = __float_as_uint(Wh [kk + qc    ][n0]);
                bh[nt][1] = __float_as_uint(Wh [kk + qc + 4][n0]);
                bl[nt][0] = __float_as_uint(Wl_[kk + qc    ][n0]);
                bl[nt][1] = __float_as_uint(Wl_[kk + qc + 4][n0]);
            }
            #pragma unroll
            for (int mt = 0; mt < 2; ++mt)
                #pragma unroll
                for (int nt = 0; nt < NT; ++nt){
                    mma8(acc[mt][nt], ah[mt][0],ah[mt][1],ah[mt][2],ah[mt][3], bh[nt][0],bh[nt][1]);
                    mma8(acc[mt][nt], ah[mt][0],ah[mt][1],ah[mt][2],ah[mt][3], bl[nt][0],bl[nt][1]);
                    mma8(acc[mt][nt], al[mt][0],al[mt][1],al[mt][2],al[mt][3], bh[nt][0],bh[nt][1]);
                }
        }
        __syncthreads();
    }

    float* Og = buf<DST>() + (size_t)blockIdx.x * 128 * NC;
    #pragma unroll
    for (int mt = 0; mt < 2; ++mt){
        #pragma unroll
        for (int nt = 0; nt < NT; ++nt){
            int row = wm + mt*16 + qr;
            int col = wn + nt*8 + qc*2;
            float2 v0 = make_float2(fmaxf(acc[mt][nt][0],0.f), fmaxf(acc[mt][nt][1],0.f));
            float2 v1 = make_float2(fmaxf(acc[mt][nt][2],0.f), fmaxf(acc[mt][nt][3],0.f));
            *(float2*)(Og + (row    )*NC + col) = v0;
            *(float2*)(Og + (row + 8)*NC + col) = v1;
        }
    }
}

// ---------------- classifier GEMM (NC=64) + fused log_softmax --------------
// src=g_h, K=128. Block tile 128x64 = complete logit rows -> reduce in smem,
// write final log_softmax straight to d_out.
__global__ void __launch_bounds__(256)
k_mma_lsm(int woff, const float* __restrict__ bias, float* __restrict__ out){
    constexpr int NC = 64;
    constexpr int NT = 4;
    __shared__ __align__(16) float smem_raw[128*65];   // 33.3KB, reused
    float (*As )[136] = (float(*)[136])smem_raw;
    float (*Wh )[136] = (float(*)[136])(smem_raw + 16*136);
    float (*Wl_)[136] = (float(*)[136])(smem_raw + 32*136);

    const int tid  = threadIdx.x;
    const int wid  = tid >> 5;
    const int lane = tid & 31;
    const int qr   = lane >> 2;
    const int qc   = lane & 3;
    const int wm   = (wid & 3) * 32;
    const int wn   = (wid >> 2) * 32;

    float acc[2][NT][4];
    #pragma unroll
    for (int nt = 0; nt < NT; ++nt){
        float b0 = bias[wn + nt*8 + qc*2];
        float b1 = bias[wn + nt*8 + qc*2 + 1];
        #pragma unroll
        for (int mt = 0; mt < 2; ++mt){
            acc[mt][nt][0] = b0; acc[mt][nt][1] = b1;
            acc[mt][nt][2] = b0; acc[mt][nt][3] = b1;
        }
    }

    const float* Ablk = buf<2>() + (size_t)blockIdx.x * 128 * 128;
    const float* Whg  = g_whi + woff;
    const float* Wlg  = g_wlo + woff;

    for (int kc = 0; kc < 8; ++kc){
        #pragma unroll
        for (int j = 0; j < 2; ++j){
            int idx = tid + j*256;
            int row = idx >> 2;
            int c4  = idx & 3;
            float4 v = *(const float4*)(Ablk + row*128 + kc*16 + c4*4);
            As[c4*4+0][row] = v.x;
            As[c4*4+1][row] = v.y;
            As[c4*4+2][row] = v.z;
            As[c4*4+3][row] = v.w;
        }
        {   // 16*64/4 = 256 float4 loads
            int row = tid >> 4;
            int c4  = tid & 15;
            *(float4*)&Wh [row][c4*4] = *(const float4*)(Whg + (kc*16+row)*NC + c4*4);
            *(float4*)&Wl_[row][c4*4] = *(const float4*)(Wlg + (kc*16+row)*NC + c4*4);
        }
        __syncthreads();

        #pragma unroll
        for (int ks = 0; ks < 2; ++ks){
            const int kk = ks*8;
            uint32_t ah[2][4], al[2][4];
            #pragma unroll
            for (int mt = 0; mt < 2; ++mt){
                int m0 = wm + mt*16 + qr;
                float f0 = As[kk + qc    ][m0];
                float f1 = As[kk + qc    ][m0 + 8];
                float f2 = As[kk + qc + 4][m0];
                float f3 = As[kk + qc + 4][m0 + 8];
                uint32_t h0 = f2tf32(f0), h1 = f2tf32(f1), h2 = f2tf32(f2), h3 = f2tf32(f3);
                ah[mt][0]=h0; ah[mt][1]=h1; ah[mt][2]=h2; ah[mt][3]=h3;
                al[mt][0]=f2tf32(f0 - __uint_as_float(h0));
                al[mt][1]=f2tf32(f1 - __uint_as_float(h1));
                al[mt][2]=f2tf32(f2 - __uint_as_float(h2));
                al[mt][3]=f2tf32(f3 - __uint_as_float(h3));
            }
            uint32_t bh[NT][2], bl[NT][2];
            #pragma unroll
            for (int nt = 0; nt < NT; ++nt){
                int n0 = wn + nt*8 + qr;
                bh[nt][0] = __float_as_uint(Wh [kk + qc    ][n0]);
                bh[nt][1] = __float_as_uint(Wh [kk + qc + 4][n0]);
                bl[nt][0] = __float_as_uint(Wl_[kk + qc    ][n0]);
                bl[nt][1] = __float_as_uint(Wl_[kk + qc + 4][n0]);
            }
            #pragma unroll
            for (int mt = 0; mt < 2; ++mt)
                #pragma unroll
                for (int nt = 0; nt < NT; ++nt){
                    mma8(acc[mt][nt], ah[mt][0],ah[mt][1],ah[mt][2],ah[mt][3], bh[nt][0],bh[nt][1]);
                    mma8(acc[mt][nt], ah[mt][0],ah[mt][1],ah[mt][2],ah[mt][3], bl[nt][0],bl[nt][1]);
                    mma8(acc[mt][nt], al[mt][0],al[mt][1],al[mt][2],al[mt][3], bh[nt][0],bh[nt][1]);
                }
        }
        __syncthreads();
    }

    // epilogue: stage logits tile [128][65] in smem, warp-per-row log_softmax
    float (*tile)[65] = (float(*)[65])smem_raw;
    #pragma unroll
    for (int mt = 0; mt < 2; ++mt)
        #pragma unroll
        for (int nt = 0; nt < NT; ++nt){
            int row = wm + mt*16 + qr;
            int col = wn + nt*8 + qc*2;
            tile[row    ][col]   = acc[mt][nt][0];
            tile[row    ][col+1] = acc[mt][nt][1];
            tile[row + 8][col]   = acc[mt][nt][2];
            tile[row + 8][col+1] = acc[mt][nt][3];
        }
    __syncthreads();

    for (int r = 0; r < 16; ++r){
        int row  = wid*16 + r;
        int node = blockIdx.x*128 + row;
        if (node >= NNODES) continue;
        float a = tile[row][lane];
        float b = tile[row][lane + 32];
        float m = fmaxf(a, b);
        #pragma unroll
        for (int o = 16; o > 0; o >>= 1) m = fmaxf(m, __shfl_xor_sync(0xffffffffu, m, o));
        float s = expf(a - m) + expf(b - m);
        #pragma unroll
        for (int o = 16; o > 0; o >>= 1) s += __shfl_xor_sync(0xffffffffu, s, o);
        float ls = m + logf(s);
        out[(size_t)node*OUTC + lane]      = a - ls;
        out[(size_t)node*OUTC + lane + 32] = b - ls;
    }
}

// ---------------- launch: kernel launches ONLY, size-based input mapping ---
extern "C" void kernel_launch(void* const* d_in, const int* in_sizes, int n_in,
                              void* d_out, int out_size){
    const float* x = 0; const void* ei = 0;
    const float* Wl = 0; const float* bl = 0;
    const float* epsv[2] = {0,0};
    const float* Wv[4]   = {0,0,0,0};
    const float* bv[4]   = {0,0,0,0};
    int neps = 0, nW = 0, nb = 0;
    for (int i = 0; i < n_in; ++i){
        long long s = in_sizes[i];
        if      (s == 6400000) x  = (const float*)d_in[i];
        else if (s == 1600000) ei = d_in[i];
        else if (s == 8192)    Wl = (const float*)d_in[i];
        else if (s == 64)      bl = (const float*)d_in[i];
        else if (s == 1   && neps < 2) epsv[neps++] = (const float*)d_in[i];
        else if (s == 16384 && nW < 4) Wv[nW++]     = (const float*)d_in[i];
        else if (s == 128  && nb  < 4) bv[nb++]     = (const float*)d_in[i];
    }
    if (!x || !ei || !Wl || !bl || neps < 2 || nW < 4 || nb < 4) return;
    float* out = (float*)d_out;

    const int EB = (NEDGES + 255) / 256;
    const int WB = (NNODES*32 + 255) / 256;

    // init (detect+zero+wsplit) + CSR build
    k_init   <<<1 + ZERO_B + WSPL_B, 256>>>((const int*)ei, Wv[0], Wv[1], Wv[2], Wv[3], Wl);
    k_hist   <<<EB, 256>>>(ei);
    k_scan1  <<<SCAN_B, 512>>>();
    k_scan3  <<<SCAN_B, 512>>>();
    k_scatter<<<EB, 256>>>(ei);

    // layer 1
    k_agg<true> <<<WB, 256>>>(x, epsv[0]);
    k_mma<0,1><<<MTILES, 256>>>(0,     bv[0]);
    k_mma<1,2><<<MTILES, 256>>>(16384, bv[1]);

    // layer 2
    k_agg<false><<<WB, 256>>>(x, epsv[1]);
    k_mma<0,1><<<MTILES, 256>>>(32768, bv[2]);
    k_mma<1,2><<<MTILES, 256>>>(49152, bv[3]);

    // classifier + fused log_softmax
    k_mma_lsm<<<MTILES, 256>>>(65536, bl, out);
}

// round 14
// speedup vs baseline: 2.4594x; 1.2795x over previous
#include <cuda_runtime.h>
#include <cuda_fp16.h>
#include <cstdint>

#define NNODES 50000
#define NEDGES 800000
#define MTILES 391
#define NPAD   (MTILES*128)   // 50048
#define HDIM   128
#define OUTC   64
#define SCAN_B 98             // ceil(50000/512)
#define ZERO_B 196            // ceil(50000/256)
#define WP_TOT (4*8192 + 4096)   // packed half2 pairs: 4x(64*128) + 64*64
#define WSPL_B 144            // WP_TOT/256

// ------------- scratch: __device__ globals, touched ONLY from device code --
__device__ __align__(16) float g_z[(size_t)NPAD*HDIM];
__device__ __align__(16) float g_t[(size_t)NPAD*HDIM];
__device__ __align__(16) float g_h[(size_t)NPAD*HDIM];
__device__ __align__(16) uint32_t g_wh2[WP_TOT];   // packed half2 (k, k+1)
__device__ __align__(16) uint32_t g_wl2[WP_TOT];
__device__ int   g_cnt[NNODES];
__device__ int   g_fill[NNODES];
__device__ int   g_rowptr[NNODES+1];
__device__ int   g_srcs[NEDGES];
__device__ int   g_bsums[SCAN_B];
__device__ int   g_is64;

// 0=g_z 1=g_t 2=g_h
template<int ID> __device__ __forceinline__ float* buf(){
    if constexpr (ID == 0) return g_z;
    else if constexpr (ID == 1) return g_t;
    else return g_h;
}

__device__ __forceinline__ int clampN(int i){
    i = max(i, 0);
    return min(i, NNODES - 1);
}

__device__ __forceinline__ uint32_t packsplit_hi(float a, float b){
    __half2 h = __halves2half2(__float2half_rn(a), __float2half_rn(b));
    return *reinterpret_cast<uint32_t*>(&h);
}
__device__ __forceinline__ uint32_t packsplit_lo(float a, float b){
    __half ha = __float2half_rn(a), hb = __float2half_rn(b);
    __half2 l = __halves2half2(__float2half_rn(a - __half2float(ha)),
                               __float2half_rn(b - __half2float(hb)));
    return *reinterpret_cast<uint32_t*>(&l);
}

__device__ __forceinline__ void mma16(float* c, uint32_t a0, uint32_t a1,
                                      uint32_t a2, uint32_t a3,
                                      uint32_t b0, uint32_t b1){
    asm("mma.sync.aligned.m16n8k16.row.col.f32.f16.f16.f32 "
        "{%0,%1,%2,%3},{%4,%5,%6,%7},{%8,%9},{%0,%1,%2,%3};"
        : "+f"(c[0]), "+f"(c[1]), "+f"(c[2]), "+f"(c[3])
        : "r"(a0), "r"(a1), "r"(a2), "r"(a3), "r"(b0), "r"(b1));
}

// ---------------- fused init: detect dtype + zero counters + split weights --
// weight pack regions (u32 idx): W11:0 W12:8192 W21:16384 W22:24576 Wl:32768
__global__ void k_init(const int* __restrict__ ei32,
                       const float* __restrict__ W0, const float* __restrict__ W1,
                       const float* __restrict__ W2, const float* __restrict__ W3,
                       const float* __restrict__ W4){
    int bid = blockIdx.x;
    if (bid == 0){
        __shared__ int anynz;
        if (threadIdx.x == 0) anynz = 0;
        __syncthreads();
        bool nz = false;
        #pragma unroll
        for (int j = 0; j < 8; ++j){
            int i = threadIdx.x*8 + j;
            if (ei32[2*i + 1] != 0) nz = true;
        }
        if (__ballot_sync(0xffffffffu, nz) && (threadIdx.x & 31) == 0)
            atomicExch(&anynz, 1);
        __syncthreads();
        if (threadIdx.x == 0) g_is64 = anynz ? 0 : 1;
    } else if (bid < 1 + ZERO_B){
        int i = (bid - 1)*256 + threadIdx.x;
        if (i < NNODES){ g_cnt[i] = 0; g_fill[i] = 0; }
    } else {
        int i = (bid - 1 - ZERO_B)*256 + threadIdx.x;
        if (i < WP_TOT){
            const float* src; int p, NC;
            if (i < 32768){
                int r = i >> 13;  p = i & 8191;  NC = 128;
                src = (r == 0) ? W0 : (r == 1) ? W1 : (r == 2) ? W2 : W3;
            } else { src = W4; p = i - 32768; NC = 64; }
            int kp = p / NC, n = p % NC, k = 2*kp;
            float w0 = src[k*NC + n];
            float w1 = src[(k+1)*NC + n];
            g_wh2[i] = packsplit_hi(w0, w1);
            g_wl2[i] = packsplit_lo(w0, w1);
        }
    }
}

// ---------------- CSR build (4 edges/thread, vectorized) --------------------
__device__ __forceinline__ void load4_dst(const void* ei, int e4, int* d){
    if (g_is64){
        const long long* p = (const long long*)ei + NEDGES + e4;
        longlong2 v0 = *(const longlong2*)p;
        longlong2 v1 = *(const longlong2*)(p + 2);
        d[0] = clampN((int)v0.x); d[1] = clampN((int)v0.y);
        d[2] = clampN((int)v1.x); d[3] = clampN((int)v1.y);
    } else {
        int4 v = *(const int4*)((const int*)ei + NEDGES + e4);
        d[0] = clampN(v.x); d[1] = clampN(v.y); d[2] = clampN(v.z); d[3] = clampN(v.w);
    }
}
__device__ __forceinline__ void load4_src(const void* ei, int e4, int* s){
    if (g_is64){
        const long long* p = (const long long*)ei + e4;
        longlong2 v0 = *(const longlong2*)p;
        longlong2 v1 = *(const longlong2*)(p + 2);
        s[0] = clampN((int)v0.x); s[1] = clampN((int)v0.y);
        s[2] = clampN((int)v1.x); s[3] = clampN((int)v1.y);
    } else {
        int4 v = *(const int4*)((const int*)ei + e4);
        s[0] = clampN(v.x); s[1] = clampN(v.y); s[2] = clampN(v.z); s[3] = clampN(v.w);
    }
}

__global__ void k_hist(const void* __restrict__ ei){
    int e4 = (blockIdx.x*blockDim.x + threadIdx.x) * 4;
    if (e4 >= NEDGES) return;
    int d[4]; load4_dst(ei, e4, d);
    #pragma unroll
    for (int j = 0; j < 4; ++j) atomicAdd(&g_cnt[d[j]], 1);
}

__global__ void k_scan1(){
    __shared__ int s[512];
    int i = blockIdx.x*512 + threadIdx.x;
    s[threadIdx.x] = (i < NNODES) ? g_cnt[i] : 0;
    __syncthreads();
    for (int st = 256; st > 0; st >>= 1){
        if (threadIdx.x < st) s[threadIdx.x] += s[threadIdx.x + st];
        __syncthreads();
    }
    if (threadIdx.x == 0) g_bsums[blockIdx.x] = s[0];
}

__global__ void k_scan3(){
    __shared__ int s[512];
    __shared__ int base;
    int i = blockIdx.x*512 + threadIdx.x;
    int v = (i < NNODES) ? g_cnt[i] : 0;
    s[threadIdx.x] = v;
    if (threadIdx.x == 0){
        int acc = 0;
        for (int j = 0; j < blockIdx.x; ++j) acc += g_bsums[j];
        base = acc;
    }
    __syncthreads();
    for (int st = 1; st < 512; st <<= 1){
        int t = 0;
        if (threadIdx.x >= st) t = s[threadIdx.x - st];
        __syncthreads();
        s[threadIdx.x] += t;
        __syncthreads();
    }
    if (i < NNODES) g_rowptr[i] = base + s[threadIdx.x] - v;
    if (i == NNODES-1) g_rowptr[NNODES] = NEDGES;
}

__global__ void k_scatter(const void* __restrict__ ei){
    int e4 = (blockIdx.x*blockDim.x + threadIdx.x) * 4;
    if (e4 >= NEDGES) return;
    int d[4], s[4];
    load4_dst(ei, e4, d);
    load4_src(ei, e4, s);
    #pragma unroll
    for (int j = 0; j < 4; ++j){
        int p = atomicAdd(&g_fill[d[j]], 1);
        int idx = g_rowptr[d[j]] + p;
        if (idx >= 0 && idx < NEDGES) g_srcs[idx] = s[j];
    }
}

// ---------------- GIN aggregation: g_z = (1+eps)*h + sum_{j in N(i)} h_j ---
template<bool FROM_X>
__global__ void k_agg(const float* __restrict__ xin, const float* __restrict__ epsp){
    int gw   = (blockIdx.x*blockDim.x + threadIdx.x) >> 5;
    int lane = threadIdx.x & 31;
    if (gw >= NNODES) return;
    const float* Hin = FROM_X ? xin : buf<2>();
    float scale = 1.0f + *epsp;
    const float4* hv = (const float4*)Hin;
    float4 self = hv[(size_t)gw*32 + lane];
    float4 acc;
    acc.x = self.x*scale; acc.y = self.y*scale;
    acc.z = self.z*scale; acc.w = self.w*scale;
    int p  = g_rowptr[gw];
    int pe = g_rowptr[gw + 1];
    while (p < pe){
        int cnt = min(pe - p, 32);
        int idx = (lane < cnt) ? g_srcs[p + lane] : 0;
        for (int j = 0; j < cnt; ++j){
            int s = __shfl_sync(0xffffffffu, idx, j);
            float4 v = hv[(size_t)s*32 + lane];
            acc.x += v.x; acc.y += v.y; acc.z += v.z; acc.w += v.w;
        }
        p += cnt;
    }
    ((float4*)buf<0>())[(size_t)gw*32 + lane] = acc;
}

// ---------------- tensor-core GEMM (split-FP16, 3 MMAs, m16n8k16) ----------
// dst[m][n] = relu( sum_k src[m][k]*W[k][n] + bias[n] ), K=128, NC=128.
// Block 256 thr = 8 warps (4m x 2n); warp tile 32m x 64n.
// K staged in 4 slabs of 32; smem holds packed half2 hi/lo for A and W.
// Row stride 136 u32 -> fragment LDS bank-conflict-free ({0,8,16,24}+qr).
template<int SRC, int DST>
__global__ void __launch_bounds__(256)
k_mma(int woff, const float* __restrict__ bias){
    constexpr int NC = 128;
    constexpr int NT = 8;
    __shared__ __align__(16) uint32_t Ah2[16][136];
    __shared__ __align__(16) uint32_t Al2[16][136];
    __shared__ __align__(16) uint32_t Wh2s[16][136];
    __shared__ __align__(16) uint32_t Wl2s[16][136];

    const int tid  = threadIdx.x;
    const int wid  = tid >> 5;
    const int lane = tid & 31;
    const int qr   = lane >> 2;
    const int qc   = lane & 3;
    const int wm   = (wid & 3) * 32;
    const int wn   = (wid >> 2) * 64;

    float acc[2][NT][4];
    #pragma unroll
    for (int nt = 0; nt < NT; ++nt){
        float b0 = bias[wn + nt*8 + qc*2];
        float b1 = bias[wn + nt*8 + qc*2 + 1];
        #pragma unroll
        for (int mt = 0; mt < 2; ++mt){
            acc[mt][nt][0] = b0; acc[mt][nt][1] = b1;
            acc[mt][nt][2] = b0; acc[mt][nt][3] = b1;
        }
    }

    const float* Ablk = buf<SRC>() + (size_t)blockIdx.x * 128 * 128;

    for (int kc = 0; kc < 4; ++kc){
        // stage A slab [128 m][32 k] -> packed half2 hi/lo, layout [kp][m]
        #pragma unroll
        for (int j = 0; j < 4; ++j){
            int idx = tid + j*256;          // 0..1023
            int row = idx >> 3;
            int c4  = idx & 7;
            float4 v = *(const float4*)(Ablk + row*128 + kc*32 + c4*4);
            Ah2[2*c4    ][row] = packsplit_hi(v.x, v.y);
            Ah2[2*c4 + 1][row] = packsplit_hi(v.z, v.w);
            Al2[2*c4    ][row] = packsplit_lo(v.x, v.y);
            Al2[2*c4 + 1][row] = packsplit_lo(v.z, v.w);
        }
        // stage W slab [16 kp][NC n] from pre-packed global
        #pragma unroll
        for (int j = 0; j < 2; ++j){
            int u  = tid + j*256;           // 0..511
            int kp = u >> 5;
            int n4 = (u & 31) * 4;
            int g  = woff + (kc*16 + kp)*NC + n4;
            *(uint4*)&Wh2s[kp][n4] = *(const uint4*)(g_wh2 + g);
            *(uint4*)&Wl2s[kp][n4] = *(const uint4*)(g_wl2 + g);
        }
        __syncthreads();

        #pragma unroll
        for (int ksub = 0; ksub < 2; ++ksub){
            const int kb = ksub*8;
            uint32_t ah[2][4], al[2][4];
            #pragma unroll
            for (int mt = 0; mt < 2; ++mt){
                int m0 = wm + mt*16 + qr;
                ah[mt][0] = Ah2[kb+qc  ][m0];   ah[mt][1] = Ah2[kb+qc  ][m0+8];
                ah[mt][2] = Ah2[kb+qc+4][m0];   ah[mt][3] = Ah2[kb+qc+4][m0+8];
                al[mt][0] = Al2[kb+qc  ][m0];   al[mt][1] = Al2[kb+qc  ][m0+8];
                al[mt][2] = Al2[kb+qc+4][m0];   al[mt][3] = Al2[kb+qc+4][m0+8];
            }
            #pragma unroll
            for (int nt = 0; nt < NT; ++nt){
                int n0 = wn + nt*8 + qr;
                uint32_t bh0 = Wh2s[kb+qc][n0], bh1 = Wh2s[kb+qc+4][n0];
                uint32_t bl0 = Wl2s[kb+qc][n0], bl1 = Wl2s[kb+qc+4][n0];
                #pragma unroll
                for (int mt = 0; mt < 2; ++mt){
                    mma16(acc[mt][nt], ah[mt][0],ah[mt][1],ah[mt][2],ah[mt][3], bh0,bh1);
                    mma16(acc[mt][nt], ah[mt][0],ah[mt][1],ah[mt][2],ah[mt][3], bl0,bl1);
                    mma16(acc[mt][nt], al[mt][0],al[mt][1],al[mt][2],al[mt][3], bh0,bh1);
                }
            }
        }
        __syncthreads();
    }

    float* Og = buf<DST>() + (size_t)blockIdx.x * 128 * NC;
    #pragma unroll
    for (int mt = 0; mt < 2; ++mt){
        #pragma unroll
        for (int nt = 0; nt < NT; ++nt){
            int row = wm + mt*16 + qr;
            int col = wn + nt*8 + qc*2;
            float2 v0 = make_float2(fmaxf(acc[mt][nt][0],0.f), fmaxf(acc[mt][nt][1],0.f));
            float2 v1 = make_float2(fmaxf(acc[mt][nt][2],0.f), fmaxf(acc[mt][nt][3],0.f));
            *(float2*)(Og + (row    )*NC + col) = v0;
            *(float2*)(Og + (row + 8)*NC + col) = v1;
        }
    }
}

// ---------------- classifier GEMM (NC=64) + fused log_softmax --------------
__global__ void __launch_bounds__(256)
k_mma_lsm(int woff, const float* __restrict__ bias, float* __restrict__ out){
    constexpr int NC = 64;
    constexpr int NT = 4;
    __shared__ __align__(16) uint32_t sm[4*16*136];   // 34.8KB, reused for tile
    uint32_t (*Ah2 )[136] = (uint32_t(*)[136])(sm);
    uint32_t (*Al2 )[136] = (uint32_t(*)[136])(sm + 16*136);
    uint32_t (*Wh2s)[136] = (uint32_t(*)[136])(sm + 32*136);
    uint32_t (*Wl2s)[136] = (uint32_t(*)[136])(sm + 48*136);

    const int tid  = threadIdx.x;
    const int wid  = tid >> 5;
    const int lane = tid & 31;
    const int qr   = lane >> 2;
    const int qc   = lane & 3;
    const int wm   = (wid & 3) * 32;
    const int wn   = (wid >> 2) * 32;

    float acc[2][NT][4];
    #pragma unroll
    for (int nt = 0; nt < NT; ++nt){
        float b0 = bias[wn + nt*8 + qc*2];
        float b1 = bias[wn + nt*8 + qc*2 + 1];
        #pragma unroll
        for (int mt = 0; mt < 2; ++mt){
            acc[mt][nt][0] = b0; acc[mt][nt][1] = b1;
            acc[mt][nt][2] = b0; acc[mt][nt][3] = b1;
        }
    }

    const float* Ablk = buf<2>() + (size_t)blockIdx.x * 128 * 128;

    for (int kc = 0; kc < 4; ++kc){
        #pragma unroll
        for (int j = 0; j < 4; ++j){
            int idx = tid + j*256;
            int row = idx >> 3;
            int c4  = idx & 7;
            float4 v = *(const float4*)(Ablk + row*128 + kc*32 + c4*4);
            Ah2[2*c4    ][row] = packsplit_hi(v.x, v.y);
            Ah2[2*c4 + 1][row] = packsplit_hi(v.z, v.w);
            Al2[2*c4    ][row] = packsplit_lo(v.x, v.y);
            Al2[2*c4 + 1][row] = packsplit_lo(v.z, v.w);
        }
        {   // 16 kp x 64 n = 1024 u32 = 256 uint4
            int kp = tid >> 4;
            int n4 = (tid & 15) * 4;
            int g  = woff + (kc*16 + kp)*NC + n4;
            *(uint4*)&Wh2s[kp][n4] = *(const uint4*)(g_wh2 + g);
            *(uint4*)&Wl2s[kp][n4] = *(const uint4*)(g_wl2 + g);
        }
        __syncthreads();

        #pragma unroll
        for (int ksub = 0; ksub < 2; ++ksub){
            const int kb = ksub*8;
            uint32_t ah[2][4], al[2][4];
            #pragma unroll
            for (int mt = 0; mt < 2; ++mt){
                int m0 = wm + mt*16 + qr;
                ah[mt][0] = Ah2[kb+qc  ][m0];   ah[mt][1] = Ah2[kb+qc  ][m0+8];
                ah[mt][2] = Ah2[kb+qc+4][m0];   ah[mt][3] = Ah2[kb+qc+4][m0+8];
                al[mt][0] = Al2[kb+qc  ][m0];   al[mt][1] = Al2[kb+qc  ][m0+8];
                al[mt][2] = Al2[kb+qc+4][m0];   al[mt][3] = Al2[kb+qc+4][m0+8];
            }
            #pragma unroll
            for (int nt = 0; nt < NT; ++nt){
                int n0 = wn + nt*8 + qr;
                uint32_t bh0 = Wh2s[kb+qc][n0], bh1 = Wh2s[kb+qc+4][n0];
                uint32_t bl0 = Wl2s[kb+qc][n0], bl1 = Wl2s[kb+qc+4][n0];
                #pragma unroll
                for (int mt = 0; mt < 2; ++mt){
                    mma16(acc[mt][nt], ah[mt][0],ah[mt][1],ah[mt][2],ah[mt][3], bh0,bh1);
                    mma16(acc[mt][nt], ah[mt][0],ah[mt][1],ah[mt][2],ah[mt][3], bl0,bl1);
                    mma16(acc[mt][nt], al[mt][0],al[mt][1],al[mt][2],al[mt][3], bh0,bh1);
                }
            }
        }
        __syncthreads();
    }

    // epilogue: stage logits tile [128][65] in smem, warp-per-row log_softmax
    float (*tile)[65] = (float(*)[65])sm;
    #pragma unroll
    for (int mt = 0; mt < 2; ++mt)
        #pragma unroll
        for (int nt = 0; nt < NT; ++nt){
            int row = wm + mt*16 + qr;
            int col = wn + nt*8 + qc*2;
            tile[row    ][col]   = acc[mt][nt][0];
            tile[row    ][col+1] = acc[mt][nt][1];
            tile[row + 8][col]   = acc[mt][nt][2];
            tile[row + 8][col+1] = acc[mt][nt][3];
        }
    __syncthreads();

    for (int r = 0; r < 16; ++r){
        int row  = wid*16 + r;
        int node = blockIdx.x*128 + row;
        if (node >= NNODES) continue;
        float a = tile[row][lane];
        float b = tile[row][lane + 32];
        float m = fmaxf(a, b);
        #pragma unroll
        for (int o = 16; o > 0; o >>= 1) m = fmaxf(m, __shfl_xor_sync(0xffffffffu, m, o));
        float s = expf(a - m) + expf(b - m);
        #pragma unroll
        for (int o = 16; o > 0; o >>= 1) s += __shfl_xor_sync(0xffffffffu, s, o);
        float ls = m + logf(s);
        out[(size_t)node*OUTC + lane]      = a - ls;
        out[(size_t)node*OUTC + lane + 32] = b - ls;
    }
}

// ---------------- launch: kernel launches ONLY, size-based input mapping ---
extern "C" void kernel_launch(void* const* d_in, const int* in_sizes, int n_in,
                              void* d_out, int out_size){
    const float* x = 0; const void* ei = 0;
    const float* Wl = 0; const float* bl = 0;
    const float* epsv[2] = {0,0};
    const float* Wv[4]   = {0,0,0,0};
    const float* bv[4]   = {0,0,0,0};
    int neps = 0, nW = 0, nb = 0;
    for (int i = 0; i < n_in; ++i){
        long long s = in_sizes[i];
        if      (s == 6400000) x  = (const float*)d_in[i];
        else if (s == 1600000) ei = d_in[i];
        else if (s == 8192)    Wl = (const float*)d_in[i];
        else if (s == 64)      bl = (const float*)d_in[i];
        else if (s == 1   && neps < 2) epsv[neps++] = (const float*)d_in[i];
        else if (s == 16384 && nW < 4) Wv[nW++]     = (const float*)d_in[i];
        else if (s == 128  && nb  < 4) bv[nb++]     = (const float*)d_in[i];
    }
    if (!x || !ei || !Wl || !bl || neps < 2 || nW < 4 || nb < 4) return;
    float* out = (float*)d_out;

    const int EB4 = (NEDGES/4 + 255) / 256;   // 4 edges per thread
    const int WB  = (NNODES*32 + 255) / 256;

    k_init   <<<1 + ZERO_B + WSPL_B, 256>>>((const int*)ei, Wv[0], Wv[1], Wv[2], Wv[3], Wl);
    k_hist   <<<EB4, 256>>>(ei);
    k_scan1  <<<SCAN_B, 512>>>();
    k_scan3  <<<SCAN_B, 512>>>();
    k_scatter<<<EB4, 256>>>(ei);

    // layer 1
    k_agg<true> <<<WB, 256>>>(x, epsv[0]);
    k_mma<0,1><<<MTILES, 256>>>(0,     bv[0]);
    k_mma<1,2><<<MTILES, 256>>>(8192,  bv[1]);

    // layer 2
    k_agg<false><<<WB, 256>>>(x, epsv[1]);
    k_mma<0,1><<<MTILES, 256>>>(16384, bv[2]);
    k_mma<1,2><<<MTILES, 256>>>(24576, bv[3]);

    // classifier + fused log_softmax
    k_mma_lsm<<<MTILES, 256>>>(32768, bl, out);
}

// round 15
// speedup vs baseline: 2.5810x; 1.0494x over previous
#include <cuda_runtime.h>
#include <cuda_fp16.h>
#include <cstdint>

#define NNODES 50000
#define NEDGES 800000
#define MTILES 391
#define NPAD   (MTILES*128)   // 50048
#define HDIM   128
#define OUTC   64
#define SCAN_B 98             // ceil(50000/512)
#define ZERO_B 196            // ceil(50000/256)
#define WP_TOT (4*8192 + 4096)   // packed half2 pairs: 4x(64*128) + 64*64
#define WSPL_B 144            // WP_TOT/256
#define XPK_B  3125           // x-pack blocks (1.6M float4 / (256*2))

// ------------- scratch: __device__ globals, touched ONLY from device code --
__device__ __align__(16) float    g_z[(size_t)NPAD*HDIM];
__device__ __align__(16) float    g_t[(size_t)NPAD*HDIM];
__device__ __align__(16) float    g_h[(size_t)NPAD*HDIM];
__device__ __align__(16) uint32_t g_xh[(size_t)NPAD*64];   // x as packed half2
__device__ __align__(16) uint32_t g_hh[(size_t)NPAD*64];   // h1 as packed half2
__device__ __align__(16) uint32_t g_wh2[WP_TOT];
__device__ __align__(16) uint32_t g_wl2[WP_TOT];
__device__ int g_cnt[NNODES];
__device__ int g_fill[NNODES];
__device__ int g_rowptr[NNODES+1];
__device__ int g_srcs[NEDGES];
__device__ int g_bsums[SCAN_B];
__device__ int g_is64;

// 0=g_z 1=g_t 2=g_h  (fp32 buffers)
template<int ID> __device__ __forceinline__ float* buf(){
    if constexpr (ID == 0) return g_z;
    else if constexpr (ID == 1) return g_t;
    else return g_h;
}

__device__ __forceinline__ int clampN(int i){
    i = max(i, 0);
    return min(i, NNODES - 1);
}

__device__ __forceinline__ uint32_t packh2(float a, float b){
    __half2 h = __floats2half2_rn(a, b);
    return *reinterpret_cast<uint32_t*>(&h);
}
__device__ __forceinline__ uint32_t packsplit_lo(float a, float b){
    __half ha = __float2half_rn(a), hb = __float2half_rn(b);
    __half2 l = __halves2half2(__float2half_rn(a - __half2float(ha)),
                               __float2half_rn(b - __half2float(hb)));
    return *reinterpret_cast<uint32_t*>(&l);
}
__device__ __forceinline__ float2 h2f2(uint32_t u){
    return __half22float2(*reinterpret_cast<__half2*>(&u));
}

__device__ __forceinline__ void mma16(float* c, uint32_t a0, uint32_t a1,
                                      uint32_t a2, uint32_t a3,
                                      uint32_t b0, uint32_t b1){
    asm("mma.sync.aligned.m16n8k16.row.col.f32.f16.f16.f32 "
        "{%0,%1,%2,%3},{%4,%5,%6,%7},{%8,%9},{%0,%1,%2,%3};"
        : "+f"(c[0]), "+f"(c[1]), "+f"(c[2]), "+f"(c[3])
        : "r"(a0), "r"(a1), "r"(a2), "r"(a3), "r"(b0), "r"(b1));
}

// ------- fused init: detect dtype + zero counters + split weights + pack x --
__global__ void k_init(const int* __restrict__ ei32, const float* __restrict__ xp,
                       const float* __restrict__ W0, const float* __restrict__ W1,
                       const float* __restrict__ W2, const float* __restrict__ W3,
                       const float* __restrict__ W4){
    int bid = blockIdx.x;
    if (bid == 0){
        __shared__ int anynz;
        if (threadIdx.x == 0) anynz = 0;
        __syncthreads();
        bool nz = false;
        #pragma unroll
        for (int j = 0; j < 8; ++j){
            int i = threadIdx.x*8 + j;
            if (ei32[2*i + 1] != 0) nz = true;
        }
        if (__ballot_sync(0xffffffffu, nz) && (threadIdx.x & 31) == 0)
            atomicExch(&anynz, 1);
        __syncthreads();
        if (threadIdx.x == 0) g_is64 = anynz ? 0 : 1;
    } else if (bid < 1 + ZERO_B){
        int i = (bid - 1)*256 + threadIdx.x;
        if (i < NNODES){ g_cnt[i] = 0; g_fill[i] = 0; }
    } else if (bid < 1 + ZERO_B + WSPL_B){
        int i = (bid - 1 - ZERO_B)*256 + threadIdx.x;
        if (i < WP_TOT){
            const float* src; int p, NC;
            if (i < 32768){
                int r = i >> 13;  p = i & 8191;  NC = 128;
                src = (r == 0) ? W0 : (r == 1) ? W1 : (r == 2) ? W2 : W3;
            } else { src = W4; p = i - 32768; NC = 64; }
            int kp = p / NC, n = p % NC, k = 2*kp;
            float w0 = src[k*NC + n];
            float w1 = src[(k+1)*NC + n];
            g_wh2[i] = packh2(w0, w1);
            g_wl2[i] = packsplit_lo(w0, w1);
        }
    } else {
        // pack x into half2 rows: 1.6M float4 -> 3.2M u32, 2 float4/thread
        int t = (bid - 1 - ZERO_B - WSPL_B)*256 + threadIdx.x;
        const float4* x4 = (const float4*)xp;
        #pragma unroll
        for (int it = 0; it < 2; ++it){
            int u = t + it*(XPK_B*256);
            if (u < NNODES*32){
                float4 v = x4[u];
                g_xh[2*u]   = packh2(v.x, v.y);
                g_xh[2*u+1] = packh2(v.z, v.w);
            }
        }
    }
}

// ---------------- CSR build (4 edges/thread, vectorized) --------------------
__device__ __forceinline__ void load4_dst(const void* ei, int e4, int* d){
    if (g_is64){
        const long long* p = (const long long*)ei + NEDGES + e4;
        longlong2 v0 = *(const longlong2*)p;
        longlong2 v1 = *(const longlong2*)(p + 2);
        d[0] = clampN((int)v0.x); d[1] = clampN((int)v0.y);
        d[2] = clampN((int)v1.x); d[3] = clampN((int)v1.y);
    } else {
        int4 v = *(const int4*)((const int*)ei + NEDGES + e4);
        d[0] = clampN(v.x); d[1] = clampN(v.y); d[2] = clampN(v.z); d[3] = clampN(v.w);
    }
}
__device__ __forceinline__ void load4_src(const void* ei, int e4, int* s){
    if (g_is64){
        const long long* p = (const long long*)ei + e4;
        longlong2 v0 = *(const longlong2*)p;
        longlong2 v1 = *(const longlong2*)(p + 2);
        s[0] = clampN((int)v0.x); s[1] = clampN((int)v0.y);
        s[2] = clampN((int)v1.x); s[3] = clampN((int)v1.y);
    } else {
        int4 v = *(const int4*)((const int*)ei + e4);
        s[0] = clampN(v.x); s[1] = clampN(v.y); s[2] = clampN(v.z); s[3] = clampN(v.w);
    }
}

__global__ void k_hist(const void* __restrict__ ei){
    int e4 = (blockIdx.x*blockDim.x + threadIdx.x) * 4;
    if (e4 >= NEDGES) return;
    int d[4]; load4_dst(ei, e4, d);
    #pragma unroll
    for (int j = 0; j < 4; ++j) atomicAdd(&g_cnt[d[j]], 1);
}

__global__ void k_scan1(){
    __shared__ int s[512];
    int i = blockIdx.x*512 + threadIdx.x;
    s[threadIdx.x] = (i < NNODES) ? g_cnt[i] : 0;
    __syncthreads();
    for (int st = 256; st > 0; st >>= 1){
        if (threadIdx.x < st) s[threadIdx.x] += s[threadIdx.x + st];
        __syncthreads();
    }
    if (threadIdx.x == 0) g_bsums[blockIdx.x] = s[0];
}

__global__ void k_scan3(){
    __shared__ int s[512];
    __shared__ int base;
    int i = blockIdx.x*512 + threadIdx.x;
    int v = (i < NNODES) ? g_cnt[i] : 0;
    s[threadIdx.x] = v;
    if (threadIdx.x == 0){
        int acc = 0;
        for (int j = 0; j < blockIdx.x; ++j) acc += g_bsums[j];
        base = acc;
    }
    __syncthreads();
    for (int st = 1; st < 512; st <<= 1){
        int t = 0;
        if (threadIdx.x >= st) t = s[threadIdx.x - st];
        __syncthreads();
        s[threadIdx.x] += t;
        __syncthreads();
    }
    if (i < NNODES) g_rowptr[i] = base + s[threadIdx.x] - v;
    if (i == NNODES-1) g_rowptr[NNODES] = NEDGES;
}

__global__ void k_scatter(const void* __restrict__ ei){
    int e4 = (blockIdx.x*blockDim.x + threadIdx.x) * 4;
    if (e4 >= NEDGES) return;
    int d[4], s[4];
    load4_dst(ei, e4, d);
    load4_src(ei, e4, s);
    #pragma unroll
    for (int j = 0; j < 4; ++j){
        int p = atomicAdd(&g_fill[d[j]], 1);
        int idx = g_rowptr[d[j]] + p;
        if (idx >= 0 && idx < NEDGES) g_srcs[idx] = s[j];
    }
}

// --------- GIN aggregation from PACKED HALF rows, fp32 accumulate ----------
// g_z[i] = (1+eps)*H[i] + sum_{j in N(i)} H[j], H = g_xh (layer1) / g_hh (layer2)
template<int SRCBUF>   // 0 = g_xh, 1 = g_hh
__global__ void k_agg(const float* __restrict__ epsp){
    int gw   = (blockIdx.x*blockDim.x + threadIdx.x) >> 5;
    int lane = threadIdx.x & 31;
    if (gw >= NNODES) return;
    const uint2* H = (const uint2*)(SRCBUF == 0 ? g_xh : g_hh);  // 32 uint2/row
    float scale = 1.0f + *epsp;
    uint2 sv = H[(size_t)gw*32 + lane];
    float2 s0 = h2f2(sv.x), s1 = h2f2(sv.y);
    float4 acc;
    acc.x = s0.x*scale; acc.y = s0.y*scale;
    acc.z = s1.x*scale; acc.w = s1.y*scale;
    int p  = g_rowptr[gw];
    int pe = g_rowptr[gw + 1];
    while (p < pe){
        int cnt = min(pe - p, 32);
        int idx = (lane < cnt) ? g_srcs[p + lane] : 0;
        for (int j = 0; j < cnt; ++j){
            int s = __shfl_sync(0xffffffffu, idx, j);
            uint2 v = H[(size_t)s*32 + lane];
            float2 v0 = h2f2(v.x), v1 = h2f2(v.y);
            acc.x += v0.x; acc.y += v0.y; acc.z += v1.x; acc.w += v1.y;
        }
        p += cnt;
    }
    ((float4*)g_z)[(size_t)gw*32 + lane] = acc;
}

// ---------------- tensor-core GEMM (split-FP16, 3 MMAs, m16n8k16) ----------
// HOUT=false: dst = fp32 buf<DST>.  HOUT=true: dst = packed half2 g_hh.
template<int SRC, int DST, bool HOUT>
__global__ void __launch_bounds__(256)
k_mma(int woff, const float* __restrict__ bias){
    constexpr int NC = 128;
    constexpr int NT = 8;
    __shared__ __align__(16) uint32_t Ah2[16][136];
    __shared__ __align__(16) uint32_t Al2[16][136];
    __shared__ __align__(16) uint32_t Wh2s[16][136];
    __shared__ __align__(16) uint32_t Wl2s[16][136];

    const int tid  = threadIdx.x;
    const int wid  = tid >> 5;
    const int lane = tid & 31;
    const int qr   = lane >> 2;
    const int qc   = lane & 3;
    const int wm   = (wid & 3) * 32;
    const int wn   = (wid >> 2) * 64;

    float acc[2][NT][4];
    #pragma unroll
    for (int nt = 0; nt < NT; ++nt){
        float b0 = bias[wn + nt*8 + qc*2];
        float b1 = bias[wn + nt*8 + qc*2 + 1];
        #pragma unroll
        for (int mt = 0; mt < 2; ++mt){
            acc[mt][nt][0] = b0; acc[mt][nt][1] = b1;
            acc[mt][nt][2] = b0; acc[mt][nt][3] = b1;
        }
    }

    const float* Ablk = buf<SRC>() + (size_t)blockIdx.x * 128 * 128;

    for (int kc = 0; kc < 4; ++kc){
        #pragma unroll
        for (int j = 0; j < 4; ++j){
            int idx = tid + j*256;
            int row = idx >> 3;
            int c4  = idx & 7;
            float4 v = *(const float4*)(Ablk + row*128 + kc*32 + c4*4);
            Ah2[2*c4    ][row] = packh2(v.x, v.y);
            Ah2[2*c4 + 1][row] = packh2(v.z, v.w);
            Al2[2*c4    ][row] = packsplit_lo(v.x, v.y);
            Al2[2*c4 + 1][row] = packsplit_lo(v.z, v.w);
        }
        #pragma unroll
        for (int j = 0; j < 2; ++j){
            int u  = tid + j*256;
            int kp = u >> 5;
            int n4 = (u & 31) * 4;
            int g  = woff + (kc*16 + kp)*NC + n4;
            *(uint4*)&Wh2s[kp][n4] = *(const uint4*)(g_wh2 + g);
            *(uint4*)&Wl2s[kp][n4] = *(const uint4*)(g_wl2 + g);
        }
        __syncthreads();

        #pragma unroll
        for (int ksub = 0; ksub < 2; ++ksub){
            const int kb = ksub*8;
            uint32_t ah[2][4], al[2][4];
            #pragma unroll
            for (int mt = 0; mt < 2; ++mt){
                int m0 = wm + mt*16 + qr;
                ah[mt][0] = Ah2[kb+qc  ][m0];   ah[mt][1] = Ah2[kb+qc  ][m0+8];
                ah[mt][2] = Ah2[kb+qc+4][m0];   ah[mt][3] = Ah2[kb+qc+4][m0+8];
                al[mt][0] = Al2[kb+qc  ][m0];   al[mt][1] = Al2[kb+qc  ][m0+8];
                al[mt][2] = Al2[kb+qc+4][m0];   al[mt][3] = Al2[kb+qc+4][m0+8];
            }
            #pragma unroll
            for (int nt = 0; nt < NT; ++nt){
                int n0 = wn + nt*8 + qr;
                uint32_t bh0 = Wh2s[kb+qc][n0], bh1 = Wh2s[kb+qc+4][n0];
                uint32_t bl0 = Wl2s[kb+qc][n0], bl1 = Wl2s[kb+qc+4][n0];
                #pragma unroll
                for (int mt = 0; mt < 2; ++mt){
                    mma16(acc[mt][nt], ah[mt][0],ah[mt][1],ah[mt][2],ah[mt][3], bh0,bh1);
                    mma16(acc[mt][nt], ah[mt][0],ah[mt][1],ah[mt][2],ah[mt][3], bl0,bl1);
                    mma16(acc[mt][nt], al[mt][0],al[mt][1],al[mt][2],al[mt][3], bh0,bh1);
                }
            }
        }
        __syncthreads();
    }

    if (HOUT){
        uint32_t* Og = g_hh + (size_t)blockIdx.x * 128 * 64;
        #pragma unroll
        for (int mt = 0; mt < 2; ++mt){
            #pragma unroll
            for (int nt = 0; nt < NT; ++nt){
                int row = wm + mt*16 + qr;
                int c2  = (wn >> 1) + nt*4 + qc;
                Og[(row    )*64 + c2] = packh2(fmaxf(acc[mt][nt][0],0.f), fmaxf(acc[mt][nt][1],0.f));
                Og[(row + 8)*64 + c2] = packh2(fmaxf(acc[mt][nt][2],0.f), fmaxf(acc[mt][nt][3],0.f));
            }
        }
    } else {
        float* Og = buf<DST>() + (size_t)blockIdx.x * 128 * NC;
        #pragma unroll
        for (int mt = 0; mt < 2; ++mt){
            #pragma unroll
            for (int nt = 0; nt < NT; ++nt){
                int row = wm + mt*16 + qr;
                int col = wn + nt*8 + qc*2;
                float2 v0 = make_float2(fmaxf(acc[mt][nt][0],0.f), fmaxf(acc[mt][nt][1],0.f));
                float2 v1 = make_float2(fmaxf(acc[mt][nt][2],0.f), fmaxf(acc[mt][nt][3],0.f));
                *(float2*)(Og + (row    )*NC + col) = v0;
                *(float2*)(Og + (row + 8)*NC + col) = v1;
            }
        }
    }
}

// ---------------- classifier GEMM (NC=64) + fused log_softmax --------------
__global__ void __launch_bounds__(256)
k_mma_lsm(int woff, const float* __restrict__ bias, float* __restrict__ out){
    constexpr int NC = 64;
    constexpr int NT = 4;
    __shared__ __align__(16) uint32_t sm[4*16*136];
    uint32_t (*Ah2 )[136] = (uint32_t(*)[136])(sm);
    uint32_t (*Al2 )[136] = (uint32_t(*)[136])(sm + 16*136);
    uint32_t (*Wh2s)[136] = (uint32_t(*)[136])(sm + 32*136);
    uint32_t (*Wl2s)[136] = (uint32_t(*)[136])(sm + 48*136);

    const int tid  = threadIdx.x;
    const int wid  = tid >> 5;
    const int lane = tid & 31;
    const int qr   = lane >> 2;
    const int qc   = lane & 3;
    const int wm   = (wid & 3) * 32;
    const int wn   = (wid >> 2) * 32;

    float acc[2][NT][4];
    #pragma unroll
    for (int nt = 0; nt < NT; ++nt){
        float b0 = bias[wn + nt*8 + qc*2];
        float b1 = bias[wn + nt*8 + qc*2 + 1];
        #pragma unroll
        for (int mt = 0; mt < 2; ++mt){
            acc[mt][nt][0] = b0; acc[mt][nt][1] = b1;
            acc[mt][nt][2] = b0; acc[mt][nt][3] = b1;
        }
    }

    const float* Ablk = buf<2>() + (size_t)blockIdx.x * 128 * 128;

    for (int kc = 0; kc < 4; ++kc){
        #pragma unroll
        for (int j = 0; j < 4; ++j){
            int idx = tid + j*256;
            int row = idx >> 3;
            int c4  = idx & 7;
            float4 v = *(const float4*)(Ablk + row*128 + kc*32 + c4*4);
            Ah2[2*c4    ][row] = packh2(v.x, v.y);
            Ah2[2*c4 + 1][row] = packh2(v.z, v.w);
            Al2[2*c4    ][row] = packsplit_lo(v.x, v.y);
            Al2[2*c4 + 1][row] = packsplit_lo(v.z, v.w);
        }
        {
            int kp = tid >> 4;
            int n4 = (tid & 15) * 4;
            int g  = woff + (kc*16 + kp)*NC + n4;
            *(uint4*)&Wh2s[kp][n4] = *(const uint4*)(g_wh2 + g);
            *(uint4*)&Wl2s[kp][n4] = *(const uint4*)(g_wl2 + g);
        }
        __syncthreads();

        #pragma unroll
        for (int ksub = 0; ksub < 2; ++ksub){
            const int kb = ksub*8;
            uint32_t ah[2][4], al[2][4];
            #pragma unroll
            for (int mt = 0; mt < 2; ++mt){
                int m0 = wm + mt*16 + qr;
                ah[mt][0] = Ah2[kb+qc  ][m0];   ah[mt][1] = Ah2[kb+qc  ][m0+8];
                ah[mt][2] = Ah2[kb+qc+4][m0];   ah[mt][3] = Ah2[kb+qc+4][m0+8];
                al[mt][0] = Al2[kb+qc  ][m0];   al[mt][1] = Al2[kb+qc  ][m0+8];
                al[mt][2] = Al2[kb+qc+4][m0];   al[mt][3] = Al2[kb+qc+4][m0+8];
            }
            #pragma unroll
            for (int nt = 0; nt < NT; ++nt){
                int n0 = wn + nt*8 + qr;
                uint32_t bh0 = Wh2s[kb+qc][n0], bh1 = Wh2s[kb+qc+4][n0];
                uint32_t bl0 = Wl2s[kb+qc][n0], bl1 = Wl2s[kb+qc+4][n0];
                #pragma unroll
                for (int mt = 0; mt < 2; ++mt){
                    mma16(acc[mt][nt], ah[mt][0],ah[mt][1],ah[mt][2],ah[mt][3], bh0,bh1);
                    mma16(acc[mt][nt], ah[mt][0],ah[mt][1],ah[mt][2],ah[mt][3], bl0,bl1);
                    mma16(acc[mt][nt], al[mt][0],al[mt][1],al[mt][2],al[mt][3], bh0,bh1);
                }
            }
        }
        __syncthreads();
    }

    float (*tile)[65] = (float(*)[65])sm;
    #pragma unroll
    for (int mt = 0; mt < 2; ++mt)
        #pragma unroll
        for (int nt = 0; nt < NT; ++nt){
            int row = wm + mt*16 + qr;
            int col = wn + nt*8 + qc*2;
            tile[row    ][col]   = acc[mt][nt][0];
            tile[row    ][col+1] = acc[mt][nt][1];
            tile[row + 8][col]   = acc[mt][nt][2];
            tile[row + 8][col+1] = acc[mt][nt][3];
        }
    __syncthreads();

    for (int r = 0; r < 16; ++r){
        int row  = wid*16 + r;
        int node = blockIdx.x*128 + row;
        if (node >= NNODES) continue;
        float a = tile[row][lane];
        float b = tile[row][lane + 32];
        float m = fmaxf(a, b);
        #pragma unroll
        for (int o = 16; o > 0; o >>= 1) m = fmaxf(m, __shfl_xor_sync(0xffffffffu, m, o));
        float s = expf(a - m) + expf(b - m);
        #pragma unroll
        for (int o = 16; o > 0; o >>= 1) s += __shfl_xor_sync(0xffffffffu, s, o);
        float ls = m + logf(s);
        out[(size_t)node*OUTC + lane]      = a - ls;
        out[(size_t)node*OUTC + lane + 32] = b - ls;
    }
}

// ---------------- launch: kernel launches ONLY, size-based input mapping ---
extern "C" void kernel_launch(void* const* d_in, const int* in_sizes, int n_in,
                              void* d_out, int out_size){
    const float* x = 0; const void* ei = 0;
    const float* Wl = 0; const float* bl = 0;
    const float* epsv[2] = {0,0};
    const float* Wv[4]   = {0,0,0,0};
    const float* bv[4]   = {0,0,0,0};
    int neps = 0, nW = 0, nb = 0;
    for (int i = 0; i < n_in; ++i){
        long long s = in_sizes[i];
        if      (s == 6400000) x  = (const float*)d_in[i];
        else if (s == 1600000) ei = d_in[i];
        else if (s == 8192)    Wl = (const float*)d_in[i];
        else if (s == 64)      bl = (const float*)d_in[i];
        else if (s == 1   && neps < 2) epsv[neps++] = (const float*)d_in[i];
        else if (s == 16384 && nW < 4) Wv[nW++]     = (const float*)d_in[i];
        else if (s == 128  && nb  < 4) bv[nb++]     = (const float*)d_in[i];
    }
    if (!x || !ei || !Wl || !bl || neps < 2 || nW < 4 || nb < 4) return;
    float* out = (float*)d_out;

    const int EB4 = (NEDGES/4 + 255) / 256;
    const int WB  = (NNODES*32 + 255) / 256;

    k_init   <<<1 + ZERO_B + WSPL_B + XPK_B, 256>>>((const int*)ei, x,
                                                    Wv[0], Wv[1], Wv[2], Wv[3], Wl);
    k_hist   <<<EB4, 256>>>(ei);
    k_scan1  <<<SCAN_B, 512>>>();
    k_scan3  <<<SCAN_B, 512>>>();
    k_scatter<<<EB4, 256>>>(ei);

    // layer 1: z = agg(x_h16); t = relu(z@W11+b11); h1 = relu(t@W12+b12) -> g_hh (half)
    k_agg<0><<<WB, 256>>>(epsv[0]);
    k_mma<0,1,false><<<MTILES, 256>>>(0,    bv[0]);
    k_mma<1,2,true ><<<MTILES, 256>>>(8192, bv[1]);

    // layer 2: z = agg(h1_h16); t = relu(z@W21+b21); h2 = relu(t@W22+b22) -> g_h (fp32)
    k_agg<1><<<WB, 256>>>(epsv[1]);
    k_mma<0,1,false><<<MTILES, 256>>>(16384, bv[2]);
    k_mma<1,2,false><<<MTILES, 256>>>(24576, bv[3]);

    // classifier + fused log_softmax
    k_mma_lsm<<<MTILES, 256>>>(32768, bl, out);
}